// round 1
// baseline (speedup 1.0000x reference)
#include <cuda_runtime.h>
#include <cstdint>

#define S_LEN   2048
#define DMODEL  2048
#define DKV     512
#define NH      32
#define NKV     8
#define HD      64

// ---------------- scratch (static device globals; no allocation) ----------------
__device__ __align__(16) int8_t g_q8[S_LEN * DMODEL];   // 4 MB
__device__ float  g_qs[S_LEN * NH];                     // quant multiplier scale
__device__ __align__(16) int8_t g_k8[S_LEN * DKV];      // 1 MB
__device__ float  g_ks[S_LEN * NKV];
__device__ __align__(16) float  g_v [S_LEN * DKV];      // 4 MB
__device__ __align__(16) float  g_attn[S_LEN * DMODEL]; // 16 MB

#define NEG_INF (__int_as_float(0xff800000))

// =====================================================================
// Kernel 1: fused QKV projection + per-(token,head) int8 quantization
//   C[m,n] = sum_k x[m,k] * W[n,k]   (both K-contiguous "NT" layout)
//   BM=128, BN=64 (= one head), BK=32, 256 threads, 8x4 thread tile
// =====================================================================
__global__ __launch_bounds__(256) void qkv_kernel(
    const float* __restrict__ x, const float* __restrict__ Wq,
    const float* __restrict__ Wk, const float* __restrict__ Wv)
{
    __shared__ float As[32][128];   // [k][m]
    __shared__ float Bs[32][68];    // [k][n], padded

    const int tid = threadIdx.x;
    const int m0  = blockIdx.y * 128;
    const int n0  = blockIdx.x * 64;

    const float* B;
    int outMode, nb;
    if (n0 < DMODEL)            { B = Wq + (size_t)n0 * DMODEL;                outMode = 0; nb = n0; }
    else if (n0 < DMODEL + DKV) { B = Wk + (size_t)(n0 - DMODEL) * DMODEL;     outMode = 1; nb = n0 - DMODEL; }
    else                        { B = Wv + (size_t)(n0 - DMODEL - DKV) * DMODEL; outMode = 2; nb = n0 - DMODEL - DKV; }

    const int ty = tid >> 4;   // 0..15 -> rows ty*8..ty*8+7
    const int tx = tid & 15;   // 0..15 -> cols tx*4..tx*4+3

    float acc[8][4];
#pragma unroll
    for (int i = 0; i < 8; i++)
#pragma unroll
        for (int j = 0; j < 4; j++) acc[i][j] = 0.f;

    for (int k0 = 0; k0 < DMODEL; k0 += 32) {
        // load A tile: 128x32 = 1024 float4, 4 per thread
#pragma unroll
        for (int i = 0; i < 4; i++) {
            int idx = tid + i * 256;          // 0..1023
            int row = idx >> 3;               // 0..127
            int kq  = (idx & 7) << 2;         // 0,4,..,28
            float4 v = *reinterpret_cast<const float4*>(&x[(size_t)(m0 + row) * DMODEL + k0 + kq]);
            As[kq + 0][row] = v.x; As[kq + 1][row] = v.y;
            As[kq + 2][row] = v.z; As[kq + 3][row] = v.w;
        }
        // load B tile: 64x32 = 512 float4, 2 per thread
#pragma unroll
        for (int i = 0; i < 2; i++) {
            int idx = tid + i * 256;          // 0..511
            int row = idx >> 3;               // 0..63
            int kq  = (idx & 7) << 2;
            float4 v = *reinterpret_cast<const float4*>(&B[(size_t)row * DMODEL + k0 + kq]);
            Bs[kq + 0][row] = v.x; Bs[kq + 1][row] = v.y;
            Bs[kq + 2][row] = v.z; Bs[kq + 3][row] = v.w;
        }
        __syncthreads();
#pragma unroll
        for (int k = 0; k < 32; k++) {
            float4 a0 = *reinterpret_cast<const float4*>(&As[k][ty * 8]);
            float4 a1 = *reinterpret_cast<const float4*>(&As[k][ty * 8 + 4]);
            float4 b  = *reinterpret_cast<const float4*>(&Bs[k][tx * 4]);
            float av[8] = {a0.x, a0.y, a0.z, a0.w, a1.x, a1.y, a1.z, a1.w};
            float bv[4] = {b.x, b.y, b.z, b.w};
#pragma unroll
            for (int i = 0; i < 8; i++)
#pragma unroll
                for (int j = 0; j < 4; j++)
                    acc[i][j] = fmaf(av[i], bv[j], acc[i][j]);
        }
        __syncthreads();
    }

    if (outMode == 2) {
#pragma unroll
        for (int i = 0; i < 8; i++) {
            int m = m0 + ty * 8 + i;
            float4 v = make_float4(acc[i][0], acc[i][1], acc[i][2], acc[i][3]);
            *reinterpret_cast<float4*>(&g_v[(size_t)m * DKV + nb + tx * 4]) = v;
        }
    } else {
#pragma unroll
        for (int i = 0; i < 8; i++) {
            int m = m0 + ty * 8 + i;
            float am = fmaxf(fmaxf(fabsf(acc[i][0]), fabsf(acc[i][1])),
                             fmaxf(fabsf(acc[i][2]), fabsf(acc[i][3])));
            // reduce over the 16 lanes sharing this row (tx = lane%16, xor<=8 stays in group)
#pragma unroll
            for (int off = 8; off; off >>= 1)
                am = fmaxf(am, __shfl_xor_sync(0xffffffffu, am, off));
            float scale = 127.f / fmaxf(am, 1e-6f);
            char4 pk;
            pk.x = (char)min(127, max(-127, __float2int_rn(acc[i][0] * scale)));
            pk.y = (char)min(127, max(-127, __float2int_rn(acc[i][1] * scale)));
            pk.z = (char)min(127, max(-127, __float2int_rn(acc[i][2] * scale)));
            pk.w = (char)min(127, max(-127, __float2int_rn(acc[i][3] * scale)));
            if (outMode == 0) {
                *reinterpret_cast<char4*>(&g_q8[(size_t)m * DMODEL + nb + tx * 4]) = pk;
                if (tx == 0) g_qs[m * NH + (nb >> 6)] = scale;
            } else {
                *reinterpret_cast<char4*>(&g_k8[(size_t)m * DKV + nb + tx * 4]) = pk;
                if (tx == 0) g_ks[m * NKV + (nb >> 6)] = scale;
            }
        }
    }
}

// =====================================================================
// Kernel 2: causal GQA attention, int8 dp4a scores + fp32 online softmax
//   one CTA per (head, 64-query block); 256 threads
//   thread t: row r = t/4 (query), c = t&3; keys interleaved kk*4+c; out dims c*16..c*16+15
// =====================================================================
__global__ __launch_bounds__(256) void attn_kernel()
{
    const int h   = blockIdx.y;
    const int qb  = gridDim.x - 1 - blockIdx.x;   // heavy blocks first
    const int kvh = h >> 2;                        // rep = 4
    const int tid = threadIdx.x;
    const int r   = tid >> 2;
    const int c   = tid & 3;
    const float sm_scale = 0.125f;                 // 64^-0.5

    __shared__ int   qs8[64][17];
    __shared__ float qfac[64];
    __shared__ int   ks8[64][17];
    __shared__ float ksinv[64];
    __shared__ float vs[64][64];
    __shared__ float ps[64][68];

    // ---- load Q tile (once) ----
    {
        int row = tid >> 2, w4 = (tid & 3) << 2;
        int4 v = *reinterpret_cast<const int4*>(
            &g_q8[(size_t)(qb * 64 + row) * DMODEL + h * 64 + (tid & 3) * 16]);
        qs8[row][w4 + 0] = v.x; qs8[row][w4 + 1] = v.y;
        qs8[row][w4 + 2] = v.z; qs8[row][w4 + 3] = v.w;
        if (tid < 64) qfac[tid] = sm_scale / g_qs[(qb * 64 + tid) * NH + h];
    }
    __syncthreads();

    const int   qglob = qb * 64 + r;
    const float qf    = qfac[r];

    float m_run = NEG_INF, l_run = 0.f;
    float o[16];
#pragma unroll
    for (int i = 0; i < 16; i++) o[i] = 0.f;

    for (int j = 0; j <= qb; j++) {
        // ---- load K block + scales + V block ----
        {
            int row = tid >> 2, w4 = (tid & 3) << 2;
            int4 v = *reinterpret_cast<const int4*>(
                &g_k8[(size_t)(j * 64 + row) * DKV + kvh * 64 + (tid & 3) * 16]);
            ks8[row][w4 + 0] = v.x; ks8[row][w4 + 1] = v.y;
            ks8[row][w4 + 2] = v.z; ks8[row][w4 + 3] = v.w;
            if (tid < 64) ksinv[tid] = 1.f / g_ks[(j * 64 + tid) * NKV + kvh];
#pragma unroll
            for (int i = 0; i < 4; i++) {
                int idx = tid + i * 256;     // 0..1023 float4s
                int vr  = idx >> 4;          // 0..63
                int vq  = (idx & 15) << 2;   // 0..60
                float4 vv = *reinterpret_cast<const float4*>(
                    &g_v[(size_t)(j * 64 + vr) * DKV + kvh * 64 + vq]);
                *reinterpret_cast<float4*>(&vs[vr][vq]) = vv;
            }
        }
        __syncthreads();

        // ---- scores: 16 interleaved keys per thread, exact int32 dp4a ----
        float sv[16];
#pragma unroll
        for (int kk = 0; kk < 16; kk++) {
            int key = kk * 4 + c;
            int accI = 0;
#pragma unroll
            for (int w = 0; w < 16; w++)
                accI = __dp4a(qs8[r][w], ks8[key][w], accI);
            float s = (float)accI * qf * ksinv[key];
            int t = j * 64 + key;
            sv[kk] = (t > qglob) ? NEG_INF : s;
        }

        // ---- online softmax (quad = 4 lanes owning one query row) ----
        float mx = sv[0];
#pragma unroll
        for (int kk = 1; kk < 16; kk++) mx = fmaxf(mx, sv[kk]);
        mx = fmaxf(mx, __shfl_xor_sync(0xffffffffu, mx, 1));
        mx = fmaxf(mx, __shfl_xor_sync(0xffffffffu, mx, 2));
        float m_new = fmaxf(m_run, mx);
        float alpha = __expf(m_run - m_new);

        float psum = 0.f;
#pragma unroll
        for (int kk = 0; kk < 16; kk++) {
            float p = __expf(sv[kk] - m_new);
            psum += p;
            ps[r][kk * 4 + c] = p;
        }
        psum += __shfl_xor_sync(0xffffffffu, psum, 1);
        psum += __shfl_xor_sync(0xffffffffu, psum, 2);
        l_run = l_run * alpha + psum;
        m_run = m_new;
#pragma unroll
        for (int i = 0; i < 16; i++) o[i] *= alpha;

        __syncwarp();   // ps produced by quad lanes (same warp)

        // ---- PV: o[d] += sum_kk p[r][kk] * v[kk][d],  d = c*16 .. c*16+15 ----
#pragma unroll 4
        for (int kk = 0; kk < 64; kk++) {
            float p = ps[r][kk];
            const float4* vrow = reinterpret_cast<const float4*>(&vs[kk][c * 16]);
            float4 v0 = vrow[0], v1 = vrow[1], v2 = vrow[2], v3 = vrow[3];
            o[0]  = fmaf(p, v0.x, o[0]);  o[1]  = fmaf(p, v0.y, o[1]);
            o[2]  = fmaf(p, v0.z, o[2]);  o[3]  = fmaf(p, v0.w, o[3]);
            o[4]  = fmaf(p, v1.x, o[4]);  o[5]  = fmaf(p, v1.y, o[5]);
            o[6]  = fmaf(p, v1.z, o[6]);  o[7]  = fmaf(p, v1.w, o[7]);
            o[8]  = fmaf(p, v2.x, o[8]);  o[9]  = fmaf(p, v2.y, o[9]);
            o[10] = fmaf(p, v2.z, o[10]); o[11] = fmaf(p, v2.w, o[11]);
            o[12] = fmaf(p, v3.x, o[12]); o[13] = fmaf(p, v3.y, o[13]);
            o[14] = fmaf(p, v3.z, o[14]); o[15] = fmaf(p, v3.w, o[15]);
        }
        __syncthreads();   // before next iteration overwrites ks8/vs
    }

    float inv_l = 1.f / l_run;
    float* dst = &g_attn[(size_t)qglob * DMODEL + h * 64 + c * 16];
#pragma unroll
    for (int i4 = 0; i4 < 4; i4++) {
        float4 v = make_float4(o[i4 * 4 + 0] * inv_l, o[i4 * 4 + 1] * inv_l,
                               o[i4 * 4 + 2] * inv_l, o[i4 * 4 + 3] * inv_l);
        *reinterpret_cast<float4*>(dst + i4 * 4) = v;
    }
}

// =====================================================================
// Kernel 3: output projection  out = attn @ Wo^T   (same tiling as K1)
// =====================================================================
__global__ __launch_bounds__(256) void out_gemm(
    const float* __restrict__ Wo, float* __restrict__ out)
{
    __shared__ float As[32][128];
    __shared__ float Bs[32][68];

    const int tid = threadIdx.x;
    const int m0  = blockIdx.y * 128;
    const int n0  = blockIdx.x * 64;
    const float* B = Wo + (size_t)n0 * DMODEL;

    const int ty = tid >> 4;
    const int tx = tid & 15;

    float acc[8][4];
#pragma unroll
    for (int i = 0; i < 8; i++)
#pragma unroll
        for (int j = 0; j < 4; j++) acc[i][j] = 0.f;

    for (int k0 = 0; k0 < DMODEL; k0 += 32) {
#pragma unroll
        for (int i = 0; i < 4; i++) {
            int idx = tid + i * 256;
            int row = idx >> 3;
            int kq  = (idx & 7) << 2;
            float4 v = *reinterpret_cast<const float4*>(&g_attn[(size_t)(m0 + row) * DMODEL + k0 + kq]);
            As[kq + 0][row] = v.x; As[kq + 1][row] = v.y;
            As[kq + 2][row] = v.z; As[kq + 3][row] = v.w;
        }
#pragma unroll
        for (int i = 0; i < 2; i++) {
            int idx = tid + i * 256;
            int row = idx >> 3;
            int kq  = (idx & 7) << 2;
            float4 v = *reinterpret_cast<const float4*>(&B[(size_t)row * DMODEL + k0 + kq]);
            Bs[kq + 0][row] = v.x; Bs[kq + 1][row] = v.y;
            Bs[kq + 2][row] = v.z; Bs[kq + 3][row] = v.w;
        }
        __syncthreads();
#pragma unroll
        for (int k = 0; k < 32; k++) {
            float4 a0 = *reinterpret_cast<const float4*>(&As[k][ty * 8]);
            float4 a1 = *reinterpret_cast<const float4*>(&As[k][ty * 8 + 4]);
            float4 b  = *reinterpret_cast<const float4*>(&Bs[k][tx * 4]);
            float av[8] = {a0.x, a0.y, a0.z, a0.w, a1.x, a1.y, a1.z, a1.w};
            float bv[4] = {b.x, b.y, b.z, b.w};
#pragma unroll
            for (int i = 0; i < 8; i++)
#pragma unroll
                for (int j = 0; j < 4; j++)
                    acc[i][j] = fmaf(av[i], bv[j], acc[i][j]);
        }
        __syncthreads();
    }

#pragma unroll
    for (int i = 0; i < 8; i++) {
        int m = m0 + ty * 8 + i;
        float4 v = make_float4(acc[i][0], acc[i][1], acc[i][2], acc[i][3]);
        *reinterpret_cast<float4*>(&out[(size_t)m * DMODEL + n0 + tx * 4]) = v;
    }
}

// =====================================================================
extern "C" void kernel_launch(void* const* d_in, const int* in_sizes, int n_in,
                              void* d_out, int out_size)
{
    const float* x  = (const float*)d_in[0];
    const float* Wq = (const float*)d_in[1];
    const float* Wk = (const float*)d_in[2];
    const float* Wv = (const float*)d_in[3];
    const float* Wo = (const float*)d_in[4];
    float* out = (float*)d_out;

    qkv_kernel<<<dim3(48, 16), 256>>>(x, Wq, Wk, Wv);   // N = 2048+512+512 cols
    attn_kernel<<<dim3(32, 32), 256>>>();               // (qb, head)
    out_gemm<<<dim3(32, 16), 256>>>(Wo, out);
}

// round 2
// speedup vs baseline: 1.9002x; 1.9002x over previous
#include <cuda_runtime.h>
#include <cstdint>

#define S_LEN   2048
#define DMODEL  2048
#define DKV     512
#define NH      32
#define NKV     8
#define HD      64

// ---------------- scratch (static device globals; no allocation) ----------------
__device__ __align__(16) int8_t g_q8[S_LEN * DMODEL];   // 4 MB
__device__ float  g_qs[S_LEN * NH];                     // quant multiplier scale
__device__ __align__(16) int8_t g_k8[S_LEN * DKV];      // 1 MB
__device__ float  g_ks[S_LEN * NKV];
__device__ __align__(16) float  g_v [S_LEN * DKV];      // 4 MB
__device__ __align__(16) float  g_attn[S_LEN * DMODEL]; // 16 MB

#define NEG_INF (__int_as_float(0xff800000))

// =====================================================================
// Kernel 1: fused QKV projection + per-(token,head) int8 quantization
//   (unchanged from round 1 — proven correct; GEMM optimization next round)
// =====================================================================
__global__ __launch_bounds__(256) void qkv_kernel(
    const float* __restrict__ x, const float* __restrict__ Wq,
    const float* __restrict__ Wk, const float* __restrict__ Wv)
{
    __shared__ float As[32][128];   // [k][m]
    __shared__ float Bs[32][68];    // [k][n], padded

    const int tid = threadIdx.x;
    const int m0  = blockIdx.y * 128;
    const int n0  = blockIdx.x * 64;

    const float* B;
    int outMode, nb;
    if (n0 < DMODEL)            { B = Wq + (size_t)n0 * DMODEL;                outMode = 0; nb = n0; }
    else if (n0 < DMODEL + DKV) { B = Wk + (size_t)(n0 - DMODEL) * DMODEL;     outMode = 1; nb = n0 - DMODEL; }
    else                        { B = Wv + (size_t)(n0 - DMODEL - DKV) * DMODEL; outMode = 2; nb = n0 - DMODEL - DKV; }

    const int ty = tid >> 4;
    const int tx = tid & 15;

    float acc[8][4];
#pragma unroll
    for (int i = 0; i < 8; i++)
#pragma unroll
        for (int j = 0; j < 4; j++) acc[i][j] = 0.f;

    for (int k0 = 0; k0 < DMODEL; k0 += 32) {
#pragma unroll
        for (int i = 0; i < 4; i++) {
            int idx = tid + i * 256;
            int row = idx >> 3;
            int kq  = (idx & 7) << 2;
            float4 v = *reinterpret_cast<const float4*>(&x[(size_t)(m0 + row) * DMODEL + k0 + kq]);
            As[kq + 0][row] = v.x; As[kq + 1][row] = v.y;
            As[kq + 2][row] = v.z; As[kq + 3][row] = v.w;
        }
#pragma unroll
        for (int i = 0; i < 2; i++) {
            int idx = tid + i * 256;
            int row = idx >> 3;
            int kq  = (idx & 7) << 2;
            float4 v = *reinterpret_cast<const float4*>(&B[(size_t)row * DMODEL + k0 + kq]);
            Bs[kq + 0][row] = v.x; Bs[kq + 1][row] = v.y;
            Bs[kq + 2][row] = v.z; Bs[kq + 3][row] = v.w;
        }
        __syncthreads();
#pragma unroll
        for (int k = 0; k < 32; k++) {
            float4 a0 = *reinterpret_cast<const float4*>(&As[k][ty * 8]);
            float4 a1 = *reinterpret_cast<const float4*>(&As[k][ty * 8 + 4]);
            float4 b  = *reinterpret_cast<const float4*>(&Bs[k][tx * 4]);
            float av[8] = {a0.x, a0.y, a0.z, a0.w, a1.x, a1.y, a1.z, a1.w};
            float bv[4] = {b.x, b.y, b.z, b.w};
#pragma unroll
            for (int i = 0; i < 8; i++)
#pragma unroll
                for (int j = 0; j < 4; j++)
                    acc[i][j] = fmaf(av[i], bv[j], acc[i][j]);
        }
        __syncthreads();
    }

    if (outMode == 2) {
#pragma unroll
        for (int i = 0; i < 8; i++) {
            int m = m0 + ty * 8 + i;
            float4 v = make_float4(acc[i][0], acc[i][1], acc[i][2], acc[i][3]);
            *reinterpret_cast<float4*>(&g_v[(size_t)m * DKV + nb + tx * 4]) = v;
        }
    } else {
#pragma unroll
        for (int i = 0; i < 8; i++) {
            int m = m0 + ty * 8 + i;
            float am = fmaxf(fmaxf(fabsf(acc[i][0]), fabsf(acc[i][1])),
                             fmaxf(fabsf(acc[i][2]), fabsf(acc[i][3])));
#pragma unroll
            for (int off = 8; off; off >>= 1)
                am = fmaxf(am, __shfl_xor_sync(0xffffffffu, am, off));
            float scale = 127.f / fmaxf(am, 1e-6f);
            char4 pk;
            pk.x = (char)min(127, max(-127, __float2int_rn(acc[i][0] * scale)));
            pk.y = (char)min(127, max(-127, __float2int_rn(acc[i][1] * scale)));
            pk.z = (char)min(127, max(-127, __float2int_rn(acc[i][2] * scale)));
            pk.w = (char)min(127, max(-127, __float2int_rn(acc[i][3] * scale)));
            if (outMode == 0) {
                *reinterpret_cast<char4*>(&g_q8[(size_t)m * DMODEL + nb + tx * 4]) = pk;
                if (tx == 0) g_qs[m * NH + (nb >> 6)] = scale;
            } else {
                *reinterpret_cast<char4*>(&g_k8[(size_t)m * DKV + nb + tx * 4]) = pk;
                if (tx == 0) g_ks[m * NKV + (nb >> 6)] = scale;
            }
        }
    }
}

// =====================================================================
// MMA helpers (warp-level tensor core PTX, sm_80+ shapes, valid on sm_100a)
// =====================================================================
__device__ __forceinline__ void mma_s8(int* c, const int* a, int b0, int b1) {
    asm volatile(
        "mma.sync.aligned.m16n8k32.row.col.s32.s8.s8.s32 "
        "{%0,%1,%2,%3}, {%4,%5,%6,%7}, {%8,%9}, {%0,%1,%2,%3};"
        : "+r"(c[0]), "+r"(c[1]), "+r"(c[2]), "+r"(c[3])
        : "r"(a[0]), "r"(a[1]), "r"(a[2]), "r"(a[3]), "r"(b0), "r"(b1));
}

__device__ __forceinline__ void mma_tf32(float* c, unsigned a0, unsigned a1,
                                         unsigned a2, unsigned a3,
                                         unsigned b0, unsigned b1) {
    asm volatile(
        "mma.sync.aligned.m16n8k8.row.col.f32.tf32.tf32.f32 "
        "{%0,%1,%2,%3}, {%4,%5,%6,%7}, {%8,%9}, {%0,%1,%2,%3};"
        : "+f"(c[0]), "+f"(c[1]), "+f"(c[2]), "+f"(c[3])
        : "r"(a0), "r"(a1), "r"(a2), "r"(a3), "r"(b0), "r"(b1));
}

__device__ __forceinline__ float tf32r(float x) {
    unsigned u;
    asm("cvt.rna.tf32.f32 %0, %1;" : "=r"(u) : "f"(x));
    return __uint_as_float(u);
}

// =====================================================================
// Kernel 2: causal GQA attention on tensor cores
//   CTA = 64 queries (4 warps x 16 rows), key blocks of 64.
//   scores: mma.s8 (exact int32);  PV: mma.tf32 (fp32 accum).
// =====================================================================
__global__ __launch_bounds__(128) void attn_kernel()
{
    const int h    = blockIdx.y;
    const int qb   = gridDim.x - 1 - blockIdx.x;   // heavy blocks first
    const int kvh  = h >> 2;                        // rep = 4
    const int tid  = threadIdx.x;
    const int warp = tid >> 5;
    const int lane = tid & 31;
    const int g    = lane >> 2;      // group 0..7
    const int tg   = lane & 3;       // 0..3
    const int rbase = warp * 16;

    __shared__ int   qsm[64][20];    // 64 tokens x 16 ints (64 int8), pitch 20
    __shared__ int   ksm[64][20];
    __shared__ float vsm[64][72];    // [key][dim], tf32-rounded, pitch 72
    __shared__ float psm[64][68];    // [row][key], tf32-rounded, pitch 68
    __shared__ float qfac[64];
    __shared__ float kinv[64];

    // ---- load Q tile (once): 256 int4 ----
#pragma unroll
    for (int i = 0; i < 2; i++) {
        int idx = tid + i * 128;
        int row = idx >> 2;
        int seg = idx & 3;
        int4 v = *reinterpret_cast<const int4*>(
            &g_q8[(size_t)(qb * 64 + row) * DMODEL + h * 64 + seg * 16]);
        *reinterpret_cast<int4*>(&qsm[row][seg * 4]) = v;
    }
    if (tid < 64) qfac[tid] = 0.125f / g_qs[(qb * 64 + tid) * NH + h];
    __syncthreads();

    // ---- Q A-fragments (2 k-steps of m16n8k32) ----
    int qa[2][4];
#pragma unroll
    for (int s = 0; s < 2; s++) {
        qa[s][0] = qsm[rbase + g    ][s * 8 + tg];
        qa[s][1] = qsm[rbase + g + 8][s * 8 + tg];
        qa[s][2] = qsm[rbase + g    ][s * 8 + 4 + tg];
        qa[s][3] = qsm[rbase + g + 8][s * 8 + 4 + tg];
    }

    const int   rowA = rbase + g, rowB = rowA + 8;
    const float qfA  = qfac[rowA], qfB = qfac[rowB];
    const int   qgA  = qb * 64 + rowA, qgB = qb * 64 + rowB;

    float acc[8][4];
#pragma unroll
    for (int nt = 0; nt < 8; nt++)
#pragma unroll
        for (int i = 0; i < 4; i++) acc[nt][i] = 0.f;
    float m_runA = NEG_INF, m_runB = NEG_INF;
    float l_runA = 0.f,     l_runB = 0.f;

    for (int j = 0; j <= qb; j++) {
        // ---- load K block, scales, V block ----
#pragma unroll
        for (int i = 0; i < 2; i++) {
            int idx = tid + i * 128;
            int row = idx >> 2;
            int seg = idx & 3;
            int4 v = *reinterpret_cast<const int4*>(
                &g_k8[(size_t)(j * 64 + row) * DKV + kvh * 64 + seg * 16]);
            *reinterpret_cast<int4*>(&ksm[row][seg * 4]) = v;
        }
        if (tid < 64) kinv[tid] = 1.f / g_ks[(j * 64 + tid) * NKV + kvh];
#pragma unroll
        for (int i = 0; i < 8; i++) {
            int idx = tid + i * 128;          // 0..1023 float4s
            int row = idx >> 4;
            int c4  = (idx & 15) << 2;
            float4 vv = *reinterpret_cast<const float4*>(
                &g_v[(size_t)(j * 64 + row) * DKV + kvh * 64 + c4]);
            vv.x = tf32r(vv.x); vv.y = tf32r(vv.y);
            vv.z = tf32r(vv.z); vv.w = tf32r(vv.w);
            *reinterpret_cast<float4*>(&vsm[row][c4]) = vv;
        }
        __syncthreads();

        // ---- scores: 8 n-tiles x 2 k-steps of m16n8k32.s8 (exact) ----
        int sc[8][4];
#pragma unroll
        for (int nt = 0; nt < 8; nt++) {
            sc[nt][0] = sc[nt][1] = sc[nt][2] = sc[nt][3] = 0;
#pragma unroll
            for (int s = 0; s < 2; s++) {
                int b0 = ksm[nt * 8 + g][s * 8 + tg];
                int b1 = ksm[nt * 8 + g][s * 8 + 4 + tg];
                mma_s8(sc[nt], qa[s], b0, b1);
            }
        }

        // ---- dequant + mask + online softmax ----
        const bool maskblk = (j == qb);
        float sv[8][4];
        float mxA = NEG_INF, mxB = NEG_INF;
#pragma unroll
        for (int nt = 0; nt < 8; nt++) {
            int colbase = nt * 8 + tg * 2;
            float2 kv = *reinterpret_cast<const float2*>(&kinv[colbase]);
            float s0 = (float)sc[nt][0] * qfA * kv.x;
            float s1 = (float)sc[nt][1] * qfA * kv.y;
            float s2 = (float)sc[nt][2] * qfB * kv.x;
            float s3 = (float)sc[nt][3] * qfB * kv.y;
            if (maskblk) {
                int col = j * 64 + colbase;
                if (col     > qgA) s0 = NEG_INF;
                if (col + 1 > qgA) s1 = NEG_INF;
                if (col     > qgB) s2 = NEG_INF;
                if (col + 1 > qgB) s3 = NEG_INF;
            }
            sv[nt][0] = s0; sv[nt][1] = s1; sv[nt][2] = s2; sv[nt][3] = s3;
            mxA = fmaxf(mxA, fmaxf(s0, s1));
            mxB = fmaxf(mxB, fmaxf(s2, s3));
        }
        mxA = fmaxf(mxA, __shfl_xor_sync(0xffffffffu, mxA, 1));
        mxA = fmaxf(mxA, __shfl_xor_sync(0xffffffffu, mxA, 2));
        mxB = fmaxf(mxB, __shfl_xor_sync(0xffffffffu, mxB, 1));
        mxB = fmaxf(mxB, __shfl_xor_sync(0xffffffffu, mxB, 2));

        float mA = fmaxf(m_runA, mxA);
        float mB = fmaxf(m_runB, mxB);
        float aA = __expf(m_runA - mA);
        float aB = __expf(m_runB - mB);
        m_runA = mA; m_runB = mB;

        float sumA = 0.f, sumB = 0.f;
#pragma unroll
        for (int nt = 0; nt < 8; nt++) {
            int colbase = nt * 8 + tg * 2;
            float p0 = __expf(sv[nt][0] - mA);
            float p1 = __expf(sv[nt][1] - mA);
            float p2 = __expf(sv[nt][2] - mB);
            float p3 = __expf(sv[nt][3] - mB);
            sumA += p0 + p1; sumB += p2 + p3;
            float2 w0 = make_float2(tf32r(p0), tf32r(p1));
            float2 w1 = make_float2(tf32r(p2), tf32r(p3));
            *reinterpret_cast<float2*>(&psm[rowA][colbase]) = w0;
            *reinterpret_cast<float2*>(&psm[rowB][colbase]) = w1;
        }
        sumA += __shfl_xor_sync(0xffffffffu, sumA, 1);
        sumA += __shfl_xor_sync(0xffffffffu, sumA, 2);
        sumB += __shfl_xor_sync(0xffffffffu, sumB, 1);
        sumB += __shfl_xor_sync(0xffffffffu, sumB, 2);
        l_runA = l_runA * aA + sumA;
        l_runB = l_runB * aB + sumB;

#pragma unroll
        for (int nt = 0; nt < 8; nt++) {
            acc[nt][0] *= aA; acc[nt][1] *= aA;
            acc[nt][2] *= aB; acc[nt][3] *= aB;
        }

        __syncwarp();   // psm rows are warp-private; order writes before reads

        // ---- PV: 8 k-steps x 8 n-tiles of m16n8k8.tf32 ----
#pragma unroll
        for (int ks = 0; ks < 8; ks++) {
            unsigned pa0 = __float_as_uint(psm[rowA][ks * 8 + tg]);
            unsigned pa1 = __float_as_uint(psm[rowB][ks * 8 + tg]);
            unsigned pa2 = __float_as_uint(psm[rowA][ks * 8 + 4 + tg]);
            unsigned pa3 = __float_as_uint(psm[rowB][ks * 8 + 4 + tg]);
#pragma unroll
            for (int nt = 0; nt < 8; nt++) {
                unsigned b0 = __float_as_uint(vsm[ks * 8 + tg    ][nt * 8 + g]);
                unsigned b1 = __float_as_uint(vsm[ks * 8 + tg + 4][nt * 8 + g]);
                mma_tf32(acc[nt], pa0, pa1, pa2, pa3, b0, b1);
            }
        }

        __syncthreads();   // before next iteration overwrites ksm/vsm
    }

    // ---- epilogue ----
    float ilA = 1.f / l_runA, ilB = 1.f / l_runB;
#pragma unroll
    for (int nt = 0; nt < 8; nt++) {
        int colbase = nt * 8 + tg * 2;
        float2 o0 = make_float2(acc[nt][0] * ilA, acc[nt][1] * ilA);
        float2 o1 = make_float2(acc[nt][2] * ilB, acc[nt][3] * ilB);
        *reinterpret_cast<float2*>(&g_attn[(size_t)qgA * DMODEL + h * 64 + colbase]) = o0;
        *reinterpret_cast<float2*>(&g_attn[(size_t)qgB * DMODEL + h * 64 + colbase]) = o1;
    }
}

// =====================================================================
// Kernel 3: output projection  out = attn @ Wo^T   (unchanged)
// =====================================================================
__global__ __launch_bounds__(256) void out_gemm(
    const float* __restrict__ Wo, float* __restrict__ out)
{
    __shared__ float As[32][128];
    __shared__ float Bs[32][68];

    const int tid = threadIdx.x;
    const int m0  = blockIdx.y * 128;
    const int n0  = blockIdx.x * 64;
    const float* B = Wo + (size_t)n0 * DMODEL;

    const int ty = tid >> 4;
    const int tx = tid & 15;

    float acc[8][4];
#pragma unroll
    for (int i = 0; i < 8; i++)
#pragma unroll
        for (int j = 0; j < 4; j++) acc[i][j] = 0.f;

    for (int k0 = 0; k0 < DMODEL; k0 += 32) {
#pragma unroll
        for (int i = 0; i < 4; i++) {
            int idx = tid + i * 256;
            int row = idx >> 3;
            int kq  = (idx & 7) << 2;
            float4 v = *reinterpret_cast<const float4*>(&g_attn[(size_t)(m0 + row) * DMODEL + k0 + kq]);
            As[kq + 0][row] = v.x; As[kq + 1][row] = v.y;
            As[kq + 2][row] = v.z; As[kq + 3][row] = v.w;
        }
#pragma unroll
        for (int i = 0; i < 2; i++) {
            int idx = tid + i * 256;
            int row = idx >> 3;
            int kq  = (idx & 7) << 2;
            float4 v = *reinterpret_cast<const float4*>(&B[(size_t)row * DMODEL + k0 + kq]);
            Bs[kq + 0][row] = v.x; Bs[kq + 1][row] = v.y;
            Bs[kq + 2][row] = v.z; Bs[kq + 3][row] = v.w;
        }
        __syncthreads();
#pragma unroll
        for (int k = 0; k < 32; k++) {
            float4 a0 = *reinterpret_cast<const float4*>(&As[k][ty * 8]);
            float4 a1 = *reinterpret_cast<const float4*>(&As[k][ty * 8 + 4]);
            float4 b  = *reinterpret_cast<const float4*>(&Bs[k][tx * 4]);
            float av[8] = {a0.x, a0.y, a0.z, a0.w, a1.x, a1.y, a1.z, a1.w};
            float bv[4] = {b.x, b.y, b.z, b.w};
#pragma unroll
            for (int i = 0; i < 8; i++)
#pragma unroll
                for (int j = 0; j < 4; j++)
                    acc[i][j] = fmaf(av[i], bv[j], acc[i][j]);
        }
        __syncthreads();
    }

#pragma unroll
    for (int i = 0; i < 8; i++) {
        int m = m0 + ty * 8 + i;
        float4 v = make_float4(acc[i][0], acc[i][1], acc[i][2], acc[i][3]);
        *reinterpret_cast<float4*>(&out[(size_t)m * DMODEL + n0 + tx * 4]) = v;
    }
}

// =====================================================================
extern "C" void kernel_launch(void* const* d_in, const int* in_sizes, int n_in,
                              void* d_out, int out_size)
{
    const float* x  = (const float*)d_in[0];
    const float* Wq = (const float*)d_in[1];
    const float* Wk = (const float*)d_in[2];
    const float* Wv = (const float*)d_in[3];
    const float* Wo = (const float*)d_in[4];
    float* out = (float*)d_out;

    qkv_kernel<<<dim3(48, 16), 256>>>(x, Wq, Wk, Wv);
    attn_kernel<<<dim3(32, 32), 128>>>();
    out_gemm<<<dim3(32, 16), 256>>>(Wo, out);
}

// round 5
// speedup vs baseline: 4.5939x; 2.4175x over previous
#include <cuda_runtime.h>
#include <cuda_bf16.h>
#include <cstdint>

#define S_LEN   2048
#define DMODEL  2048
#define DKV     512
#define NH      32
#define NKV     8
#define HD      64

// ---------------- scratch (static device globals; no allocation) ----------------
__device__ __align__(16) int8_t g_q8[S_LEN * DMODEL];   // 4 MB
__device__ float  g_qs[S_LEN * NH];
__device__ __align__(16) int8_t g_k8[S_LEN * DKV];      // 1 MB
__device__ float  g_ks[S_LEN * NKV];
__device__ __align__(16) float  g_v [S_LEN * DKV];      // 4 MB
__device__ __align__(16) float  g_attn[S_LEN * DMODEL]; // 16 MB

#define NEG_INF (__int_as_float(0xff800000))

// =====================================================================
// warp-level MMA helpers (sm_80+ shapes; compile for compute_100 baseline)
// =====================================================================
__device__ __forceinline__ void mma_bf16(float* c, const uint32_t* a,
                                         uint32_t b0, uint32_t b1) {
    asm volatile(
        "mma.sync.aligned.m16n8k16.row.col.f32.bf16.bf16.f32 "
        "{%0,%1,%2,%3}, {%4,%5,%6,%7}, {%8,%9}, {%0,%1,%2,%3};"
        : "+f"(c[0]), "+f"(c[1]), "+f"(c[2]), "+f"(c[3])
        : "r"(a[0]), "r"(a[1]), "r"(a[2]), "r"(a[3]), "r"(b0), "r"(b1));
}

__device__ __forceinline__ void mma_s8(int* c, const int* a, int b0, int b1) {
    asm volatile(
        "mma.sync.aligned.m16n8k32.row.col.s32.s8.s8.s32 "
        "{%0,%1,%2,%3}, {%4,%5,%6,%7}, {%8,%9}, {%0,%1,%2,%3};"
        : "+r"(c[0]), "+r"(c[1]), "+r"(c[2]), "+r"(c[3])
        : "r"(a[0]), "r"(a[1]), "r"(a[2]), "r"(a[3]), "r"(b0), "r"(b1));
}

__device__ __forceinline__ void mma_tf32(float* c, unsigned a0, unsigned a1,
                                         unsigned a2, unsigned a3,
                                         unsigned b0, unsigned b1) {
    asm volatile(
        "mma.sync.aligned.m16n8k8.row.col.f32.tf32.tf32.f32 "
        "{%0,%1,%2,%3}, {%4,%5,%6,%7}, {%8,%9}, {%0,%1,%2,%3};"
        : "+f"(c[0]), "+f"(c[1]), "+f"(c[2]), "+f"(c[3])
        : "r"(a0), "r"(a1), "r"(a2), "r"(a3), "r"(b0), "r"(b1));
}

__device__ __forceinline__ float tf32r(float x) {
    unsigned u;
    asm("cvt.rna.tf32.f32 %0, %1;" : "=r"(u) : "f"(x));
    return __uint_as_float(u);
}

#define LDSM4(r, a) \
    asm volatile("ldmatrix.sync.aligned.m8n8.x4.shared.b16 {%0,%1,%2,%3}, [%4];" \
                 : "=r"((r)[0]), "=r"((r)[1]), "=r"((r)[2]), "=r"((r)[3]) : "r"(a))

__device__ __forceinline__ uint32_t smem_u32(const void* p) {
    uint32_t a;
    asm("{ .reg .u64 t; cvta.to.shared.u64 t, %1; cvt.u32.u64 %0, t; }" : "=r"(a) : "l"(p));
    return a;
}

__device__ __forceinline__ uint32_t packbf2(__nv_bfloat16 a, __nv_bfloat16 b) {
    __nv_bfloat162 p; p.x = a; p.y = b;
    return *reinterpret_cast<uint32_t*>(&p);
}

// =====================================================================
// Tensor-core GEMM: C[128x128] = A[M,2048] * B[N,2048]^T, fp32-exactish via
// bf16 hi/lo 3-term (Ah*Bh + Ah*Bl + Al*Bh), fp32 accum.
//   flavor 0: A=x, B=Wq/Wk/Wv per tile -> fused int8 quant (Q,K) or V store
//   flavor 1: A=g_attn, B=Wo -> fp32 store to out
// smem per buffer: Ah,Al,Bh,Bl each 128 rows x 40 bf16 (pitch 80B) = 10240B
// =====================================================================
#define GP       80          // smem row pitch bytes
#define TILE_B   10240       // one tensor tile
#define BUF_B    40960       // 4 tiles
#define SMEM_DYN 81920       // 2 buffers

__global__ __launch_bounds__(256) void tc_gemm(
    const float* __restrict__ Aarg, const float* __restrict__ B0,
    const float* __restrict__ B1,   const float* __restrict__ B2,
    float* __restrict__ outp, int flavor)
{
    extern __shared__ char smem[];
    const uint32_t sbase = smem_u32(smem);
    const int tid  = threadIdx.x;
    const int wid  = tid >> 5;
    const int lane = tid & 31;
    const int m0   = blockIdx.y * 128;
    const int n0   = blockIdx.x * 128;
    const int wm   = (wid & 3) * 32;
    const int wn   = (wid >> 2) * 64;

    const float* A = (flavor == 1) ? g_attn : Aarg;
    const float* Bbase;
    int mode;                                  // 0=Qquant 1=Kquant 2=V 3=out
    if (flavor == 1)      { Bbase = B0 + (size_t)n0 * DMODEL;          mode = 3; }
    else if (n0 < 2048)   { Bbase = B0 + (size_t)n0 * DMODEL;          mode = 0; }
    else if (n0 < 2560)   { Bbase = B1 + (size_t)(n0 - 2048) * DMODEL; mode = 1; }
    else                  { Bbase = B2 + (size_t)(n0 - 2560) * DMODEL; mode = 2; }
    const float* Abase = A + (size_t)m0 * DMODEL;

    // per-thread staging indices: 4 float4 per tensor per iter
    const int ldRow = tid >> 3;          // 0..31 (row step 32 over 4 iters)
    const int ldC4  = (tid & 7) << 2;    // elem col 0,4,..,28

    // ldmatrix base addresses
    const uint32_t aAddr = sbase + (wm + (lane & 15)) * GP + ((lane >> 4) << 4);
    const uint32_t bAddr = sbase + 2 * TILE_B +
        (wn + (lane & 7) + ((lane >> 4) & 1) * 8) * GP + (((lane >> 3) & 1) << 4);

    float acc[2][8][4];
#pragma unroll
    for (int mt = 0; mt < 2; mt++)
#pragma unroll
        for (int nt = 0; nt < 8; nt++)
#pragma unroll
            for (int i = 0; i < 4; i++) acc[mt][nt][i] = 0.f;

    float4 ra[4], rb[4];

    // prologue: load + store iter 0
#pragma unroll
    for (int i = 0; i < 4; i++) {
        int row = ldRow + i * 32;
        ra[i] = *reinterpret_cast<const float4*>(&Abase[(size_t)row * DMODEL + ldC4]);
        rb[i] = *reinterpret_cast<const float4*>(&Bbase[(size_t)row * DMODEL + ldC4]);
    }
    {
        char* bp = smem;   // buffer 0
#pragma unroll
        for (int i = 0; i < 4; i++) {
            int row = ldRow + i * 32;
            int off = row * GP + ldC4 * 2;
            float4 v = ra[i];
            __nv_bfloat16 h0 = __float2bfloat16(v.x), h1 = __float2bfloat16(v.y);
            __nv_bfloat16 h2 = __float2bfloat16(v.z), h3 = __float2bfloat16(v.w);
            *reinterpret_cast<uint2*>(bp + off) =
                make_uint2(packbf2(h0, h1), packbf2(h2, h3));
            *reinterpret_cast<uint2*>(bp + off + TILE_B) = make_uint2(
                packbf2(__float2bfloat16(v.x - __bfloat162float(h0)),
                        __float2bfloat16(v.y - __bfloat162float(h1))),
                packbf2(__float2bfloat16(v.z - __bfloat162float(h2)),
                        __float2bfloat16(v.w - __bfloat162float(h3))));
            v = rb[i];
            h0 = __float2bfloat16(v.x); h1 = __float2bfloat16(v.y);
            h2 = __float2bfloat16(v.z); h3 = __float2bfloat16(v.w);
            *reinterpret_cast<uint2*>(bp + off + 2 * TILE_B) =
                make_uint2(packbf2(h0, h1), packbf2(h2, h3));
            *reinterpret_cast<uint2*>(bp + off + 3 * TILE_B) = make_uint2(
                packbf2(__float2bfloat16(v.x - __bfloat162float(h0)),
                        __float2bfloat16(v.y - __bfloat162float(h1))),
                packbf2(__float2bfloat16(v.z - __bfloat162float(h2)),
                        __float2bfloat16(v.w - __bfloat162float(h3))));
        }
    }

    for (int it = 0; it < 64; it++) {
        __syncthreads();
        const int buf = it & 1;

        if (it < 63) {
            const int kc = (it + 1) * 32;
#pragma unroll
            for (int i = 0; i < 4; i++) {
                int row = ldRow + i * 32;
                ra[i] = *reinterpret_cast<const float4*>(&Abase[(size_t)row * DMODEL + kc + ldC4]);
                rb[i] = *reinterpret_cast<const float4*>(&Bbase[(size_t)row * DMODEL + kc + ldC4]);
            }
        }

        // ---- compute from smem[buf] ----
        const uint32_t ab = aAddr + buf * BUF_B;
        const uint32_t bb = bAddr + buf * BUF_B;
#pragma unroll
        for (int s = 0; s < 2; s++) {
            uint32_t ah[2][4], al[2][4], bh[4][4], bl[4][4];
#pragma unroll
            for (int mt = 0; mt < 2; mt++) {
                LDSM4(ah[mt], ab + mt * (16 * GP) + s * 32);
                LDSM4(al[mt], ab + mt * (16 * GP) + s * 32 + TILE_B);
            }
#pragma unroll
            for (int np = 0; np < 4; np++) {
                LDSM4(bh[np], bb + np * (16 * GP) + s * 32);
                LDSM4(bl[np], bb + np * (16 * GP) + s * 32 + TILE_B);
            }
#pragma unroll
            for (int mt = 0; mt < 2; mt++)
#pragma unroll
                for (int nt = 0; nt < 8; nt++) {
                    uint32_t h0 = bh[nt >> 1][(nt & 1) * 2];
                    uint32_t h1 = bh[nt >> 1][(nt & 1) * 2 + 1];
                    uint32_t l0 = bl[nt >> 1][(nt & 1) * 2];
                    uint32_t l1 = bl[nt >> 1][(nt & 1) * 2 + 1];
                    mma_bf16(acc[mt][nt], ah[mt], h0, h1);
                    mma_bf16(acc[mt][nt], ah[mt], l0, l1);
                    mma_bf16(acc[mt][nt], al[mt], h0, h1);
                }
        }

        if (it < 63) {
            char* bp = smem + ((it + 1) & 1) * BUF_B;
#pragma unroll
            for (int i = 0; i < 4; i++) {
                int row = ldRow + i * 32;
                int off = row * GP + ldC4 * 2;
                float4 v = ra[i];
                __nv_bfloat16 h0 = __float2bfloat16(v.x), h1 = __float2bfloat16(v.y);
                __nv_bfloat16 h2 = __float2bfloat16(v.z), h3 = __float2bfloat16(v.w);
                *reinterpret_cast<uint2*>(bp + off) =
                    make_uint2(packbf2(h0, h1), packbf2(h2, h3));
                *reinterpret_cast<uint2*>(bp + off + TILE_B) = make_uint2(
                    packbf2(__float2bfloat16(v.x - __bfloat162float(h0)),
                            __float2bfloat16(v.y - __bfloat162float(h1))),
                    packbf2(__float2bfloat16(v.z - __bfloat162float(h2)),
                            __float2bfloat16(v.w - __bfloat162float(h3))));
                v = rb[i];
                h0 = __float2bfloat16(v.x); h1 = __float2bfloat16(v.y);
                h2 = __float2bfloat16(v.z); h3 = __float2bfloat16(v.w);
                *reinterpret_cast<uint2*>(bp + off + 2 * TILE_B) =
                    make_uint2(packbf2(h0, h1), packbf2(h2, h3));
                *reinterpret_cast<uint2*>(bp + off + 3 * TILE_B) = make_uint2(
                    packbf2(__float2bfloat16(v.x - __bfloat162float(h0)),
                            __float2bfloat16(v.y - __bfloat162float(h1))),
                    packbf2(__float2bfloat16(v.z - __bfloat162float(h2)),
                            __float2bfloat16(v.w - __bfloat162float(h3))));
            }
        }
    }

    // ---- epilogue ----
    const int qrow = lane >> 2;          // 0..7
    const int qcol = (lane & 3) * 2;
#pragma unroll
    for (int mt = 0; mt < 2; mt++) {
#pragma unroll
        for (int h = 0; h < 2; h++) {
            const int row = m0 + wm + mt * 16 + qrow + h * 8;
            if (mode <= 1) {
                float am = 0.f;
#pragma unroll
                for (int nt = 0; nt < 8; nt++)
                    am = fmaxf(am, fmaxf(fabsf(acc[mt][nt][h * 2]),
                                         fabsf(acc[mt][nt][h * 2 + 1])));
                am = fmaxf(am, __shfl_xor_sync(0xffffffffu, am, 1));
                am = fmaxf(am, __shfl_xor_sync(0xffffffffu, am, 2));
                float scale = 127.f / fmaxf(am, 1e-6f);
#pragma unroll
                for (int nt = 0; nt < 8; nt++) {
                    int v0 = min(127, max(-127, __float2int_rn(acc[mt][nt][h * 2]     * scale)));
                    int v1 = min(127, max(-127, __float2int_rn(acc[mt][nt][h * 2 + 1] * scale)));
                    unsigned short pk = (unsigned short)((v0 & 255) | ((v1 & 255) << 8));
                    if (mode == 0)
                        *reinterpret_cast<unsigned short*>(
                            &g_q8[(size_t)row * DMODEL + n0 + wn + nt * 8 + qcol]) = pk;
                    else
                        *reinterpret_cast<unsigned short*>(
                            &g_k8[(size_t)row * DKV + (n0 - 2048) + wn + nt * 8 + qcol]) = pk;
                }
                if ((lane & 3) == 0) {
                    if (mode == 0) g_qs[row * NH  + ((n0 + wn) >> 6)]        = scale;
                    else           g_ks[row * NKV + ((n0 - 2048 + wn) >> 6)] = scale;
                }
            } else {
#pragma unroll
                for (int nt = 0; nt < 8; nt++) {
                    float2 v = make_float2(acc[mt][nt][h * 2], acc[mt][nt][h * 2 + 1]);
                    if (mode == 2)
                        *reinterpret_cast<float2*>(
                            &g_v[(size_t)row * DKV + (n0 - 2560) + wn + nt * 8 + qcol]) = v;
                    else
                        *reinterpret_cast<float2*>(
                            &outp[(size_t)row * DMODEL + n0 + wn + nt * 8 + qcol]) = v;
                }
            }
        }
    }
}

// =====================================================================
// Attention kernel (round-2 design, passed at rel_err 2.6e-4)
// =====================================================================
__global__ __launch_bounds__(128) void attn_kernel()
{
    const int h    = blockIdx.y;
    const int qb   = gridDim.x - 1 - blockIdx.x;
    const int kvh  = h >> 2;
    const int tid  = threadIdx.x;
    const int warp = tid >> 5;
    const int lane = tid & 31;
    const int g    = lane >> 2;
    const int tg   = lane & 3;
    const int rbase = warp * 16;

    __shared__ int   qsm[64][20];
    __shared__ int   ksm[64][20];
    __shared__ float vsm[64][72];
    __shared__ float psm[64][68];
    __shared__ float qfac[64];
    __shared__ float kinv[64];

#pragma unroll
    for (int i = 0; i < 2; i++) {
        int idx = tid + i * 128;
        int row = idx >> 2;
        int seg = idx & 3;
        int4 v = *reinterpret_cast<const int4*>(
            &g_q8[(size_t)(qb * 64 + row) * DMODEL + h * 64 + seg * 16]);
        *reinterpret_cast<int4*>(&qsm[row][seg * 4]) = v;
    }
    if (tid < 64) qfac[tid] = 0.125f / g_qs[(qb * 64 + tid) * NH + h];
    __syncthreads();

    int qa[2][4];
#pragma unroll
    for (int s = 0; s < 2; s++) {
        qa[s][0] = qsm[rbase + g    ][s * 8 + tg];
        qa[s][1] = qsm[rbase + g + 8][s * 8 + tg];
        qa[s][2] = qsm[rbase + g    ][s * 8 + 4 + tg];
        qa[s][3] = qsm[rbase + g + 8][s * 8 + 4 + tg];
    }

    const int   rowA = rbase + g, rowB = rowA + 8;
    const float qfA  = qfac[rowA], qfB = qfac[rowB];
    const int   qgA  = qb * 64 + rowA, qgB = qb * 64 + rowB;

    float acc[8][4];
#pragma unroll
    for (int nt = 0; nt < 8; nt++)
#pragma unroll
        for (int i = 0; i < 4; i++) acc[nt][i] = 0.f;
    float m_runA = NEG_INF, m_runB = NEG_INF;
    float l_runA = 0.f,     l_runB = 0.f;

    for (int j = 0; j <= qb; j++) {
#pragma unroll
        for (int i = 0; i < 2; i++) {
            int idx = tid + i * 128;
            int row = idx >> 2;
            int seg = idx & 3;
            int4 v = *reinterpret_cast<const int4*>(
                &g_k8[(size_t)(j * 64 + row) * DKV + kvh * 64 + seg * 16]);
            *reinterpret_cast<int4*>(&ksm[row][seg * 4]) = v;
        }
        if (tid < 64) kinv[tid] = 1.f / g_ks[(j * 64 + tid) * NKV + kvh];
#pragma unroll
        for (int i = 0; i < 8; i++) {
            int idx = tid + i * 128;
            int row = idx >> 4;
            int c4  = (idx & 15) << 2;
            float4 vv = *reinterpret_cast<const float4*>(
                &g_v[(size_t)(j * 64 + row) * DKV + kvh * 64 + c4]);
            vv.x = tf32r(vv.x); vv.y = tf32r(vv.y);
            vv.z = tf32r(vv.z); vv.w = tf32r(vv.w);
            *reinterpret_cast<float4*>(&vsm[row][c4]) = vv;
        }
        __syncthreads();

        int sc[8][4];
#pragma unroll
        for (int nt = 0; nt < 8; nt++) {
            sc[nt][0] = sc[nt][1] = sc[nt][2] = sc[nt][3] = 0;
#pragma unroll
            for (int s = 0; s < 2; s++) {
                int b0 = ksm[nt * 8 + g][s * 8 + tg];
                int b1 = ksm[nt * 8 + g][s * 8 + 4 + tg];
                mma_s8(sc[nt], qa[s], b0, b1);
            }
        }

        const bool maskblk = (j == qb);
        float sv[8][4];
        float mxA = NEG_INF, mxB = NEG_INF;
#pragma unroll
        for (int nt = 0; nt < 8; nt++) {
            int colbase = nt * 8 + tg * 2;
            float2 kv = *reinterpret_cast<const float2*>(&kinv[colbase]);
            float s0 = (float)sc[nt][0] * qfA * kv.x;
            float s1 = (float)sc[nt][1] * qfA * kv.y;
            float s2 = (float)sc[nt][2] * qfB * kv.x;
            float s3 = (float)sc[nt][3] * qfB * kv.y;
            if (maskblk) {
                int col = j * 64 + colbase;
                if (col     > qgA) s0 = NEG_INF;
                if (col + 1 > qgA) s1 = NEG_INF;
                if (col     > qgB) s2 = NEG_INF;
                if (col + 1 > qgB) s3 = NEG_INF;
            }
            sv[nt][0] = s0; sv[nt][1] = s1; sv[nt][2] = s2; sv[nt][3] = s3;
            mxA = fmaxf(mxA, fmaxf(s0, s1));
            mxB = fmaxf(mxB, fmaxf(s2, s3));
        }
        mxA = fmaxf(mxA, __shfl_xor_sync(0xffffffffu, mxA, 1));
        mxA = fmaxf(mxA, __shfl_xor_sync(0xffffffffu, mxA, 2));
        mxB = fmaxf(mxB, __shfl_xor_sync(0xffffffffu, mxB, 1));
        mxB = fmaxf(mxB, __shfl_xor_sync(0xffffffffu, mxB, 2));

        float mA = fmaxf(m_runA, mxA);
        float mB = fmaxf(m_runB, mxB);
        float aA = __expf(m_runA - mA);
        float aB = __expf(m_runB - mB);
        m_runA = mA; m_runB = mB;

        float sumA = 0.f, sumB = 0.f;
#pragma unroll
        for (int nt = 0; nt < 8; nt++) {
            int colbase = nt * 8 + tg * 2;
            float p0 = __expf(sv[nt][0] - mA);
            float p1 = __expf(sv[nt][1] - mA);
            float p2 = __expf(sv[nt][2] - mB);
            float p3 = __expf(sv[nt][3] - mB);
            sumA += p0 + p1; sumB += p2 + p3;
            float2 w0 = make_float2(tf32r(p0), tf32r(p1));
            float2 w1 = make_float2(tf32r(p2), tf32r(p3));
            *reinterpret_cast<float2*>(&psm[rowA][colbase]) = w0;
            *reinterpret_cast<float2*>(&psm[rowB][colbase]) = w1;
        }
        sumA += __shfl_xor_sync(0xffffffffu, sumA, 1);
        sumA += __shfl_xor_sync(0xffffffffu, sumA, 2);
        sumB += __shfl_xor_sync(0xffffffffu, sumB, 1);
        sumB += __shfl_xor_sync(0xffffffffu, sumB, 2);
        l_runA = l_runA * aA + sumA;
        l_runB = l_runB * aB + sumB;

#pragma unroll
        for (int nt = 0; nt < 8; nt++) {
            acc[nt][0] *= aA; acc[nt][1] *= aA;
            acc[nt][2] *= aB; acc[nt][3] *= aB;
        }

        __syncwarp();

#pragma unroll
        for (int ks = 0; ks < 8; ks++) {
            unsigned pa0 = __float_as_uint(psm[rowA][ks * 8 + tg]);
            unsigned pa1 = __float_as_uint(psm[rowB][ks * 8 + tg]);
            unsigned pa2 = __float_as_uint(psm[rowA][ks * 8 + 4 + tg]);
            unsigned pa3 = __float_as_uint(psm[rowB][ks * 8 + 4 + tg]);
#pragma unroll
            for (int nt = 0; nt < 8; nt++) {
                unsigned b0 = __float_as_uint(vsm[ks * 8 + tg    ][nt * 8 + g]);
                unsigned b1 = __float_as_uint(vsm[ks * 8 + tg + 4][nt * 8 + g]);
                mma_tf32(acc[nt], pa0, pa1, pa2, pa3, b0, b1);
            }
        }

        __syncthreads();
    }

    float ilA = 1.f / l_runA, ilB = 1.f / l_runB;
#pragma unroll
    for (int nt = 0; nt < 8; nt++) {
        int colbase = nt * 8 + tg * 2;
        float2 o0 = make_float2(acc[nt][0] * ilA, acc[nt][1] * ilA);
        float2 o1 = make_float2(acc[nt][2] * ilB, acc[nt][3] * ilB);
        *reinterpret_cast<float2*>(&g_attn[(size_t)qgA * DMODEL + h * 64 + colbase]) = o0;
        *reinterpret_cast<float2*>(&g_attn[(size_t)qgB * DMODEL + h * 64 + colbase]) = o1;
    }
}

// =====================================================================
extern "C" void kernel_launch(void* const* d_in, const int* in_sizes, int n_in,
                              void* d_out, int out_size)
{
    const float* x  = (const float*)d_in[0];
    const float* Wq = (const float*)d_in[1];
    const float* Wk = (const float*)d_in[2];
    const float* Wv = (const float*)d_in[3];
    const float* Wo = (const float*)d_in[4];
    float* out = (float*)d_out;

    cudaFuncSetAttribute(tc_gemm, cudaFuncAttributeMaxDynamicSharedMemorySize, SMEM_DYN);

    tc_gemm<<<dim3(24, 16), 256, SMEM_DYN>>>(x, Wq, Wk, Wv, nullptr, 0);  // QKV
    attn_kernel<<<dim3(32, 32), 128>>>();
    tc_gemm<<<dim3(16, 16), 256, SMEM_DYN>>>(nullptr, Wo, nullptr, nullptr, out, 1);
}

// round 6
// speedup vs baseline: 4.6882x; 1.0205x over previous
#include <cuda_runtime.h>
#include <cuda_bf16.h>
#include <cstdint>

#define S_LEN   2048
#define DMODEL  2048
#define DKV     512
#define NH      32
#define NKV     8
#define HD      64

// ---------------- scratch (static device globals; no allocation) ----------------
__device__ __align__(16) int8_t g_q8[S_LEN * DMODEL];   // 4 MB
__device__ float  g_qs[S_LEN * NH];
__device__ __align__(16) int8_t g_k8[S_LEN * DKV];      // 1 MB
__device__ float  g_ks[S_LEN * NKV];
__device__ __align__(16) float  g_v [S_LEN * DKV];      // 4 MB

// bf16 hi/lo split buffers
__device__ __align__(16) __nv_bfloat16 g_xh[S_LEN * DMODEL],   g_xl[S_LEN * DMODEL];
__device__ __align__(16) __nv_bfloat16 g_wh[3072 * DMODEL],    g_wl[3072 * DMODEL];
__device__ __align__(16) __nv_bfloat16 g_woh[DMODEL * DMODEL], g_wol[DMODEL * DMODEL];
__device__ __align__(16) __nv_bfloat16 g_ah[S_LEN * DMODEL],   g_al[S_LEN * DMODEL];

#define NEG_INF (__int_as_float(0xff800000))

// =====================================================================
// helpers
// =====================================================================
__device__ __forceinline__ void mma_bf16(float* c, const uint32_t* a,
                                         uint32_t b0, uint32_t b1) {
    asm volatile(
        "mma.sync.aligned.m16n8k16.row.col.f32.bf16.bf16.f32 "
        "{%0,%1,%2,%3}, {%4,%5,%6,%7}, {%8,%9}, {%0,%1,%2,%3};"
        : "+f"(c[0]), "+f"(c[1]), "+f"(c[2]), "+f"(c[3])
        : "r"(a[0]), "r"(a[1]), "r"(a[2]), "r"(a[3]), "r"(b0), "r"(b1));
}

__device__ __forceinline__ void mma_s8(int* c, const int* a, int b0, int b1) {
    asm volatile(
        "mma.sync.aligned.m16n8k32.row.col.s32.s8.s8.s32 "
        "{%0,%1,%2,%3}, {%4,%5,%6,%7}, {%8,%9}, {%0,%1,%2,%3};"
        : "+r"(c[0]), "+r"(c[1]), "+r"(c[2]), "+r"(c[3])
        : "r"(a[0]), "r"(a[1]), "r"(a[2]), "r"(a[3]), "r"(b0), "r"(b1));
}

__device__ __forceinline__ void mma_tf32(float* c, unsigned a0, unsigned a1,
                                         unsigned a2, unsigned a3,
                                         unsigned b0, unsigned b1) {
    asm volatile(
        "mma.sync.aligned.m16n8k8.row.col.f32.tf32.tf32.f32 "
        "{%0,%1,%2,%3}, {%4,%5,%6,%7}, {%8,%9}, {%0,%1,%2,%3};"
        : "+f"(c[0]), "+f"(c[1]), "+f"(c[2]), "+f"(c[3])
        : "r"(a0), "r"(a1), "r"(a2), "r"(a3), "r"(b0), "r"(b1));
}

__device__ __forceinline__ float tf32r(float x) {
    unsigned u;
    asm("cvt.rna.tf32.f32 %0, %1;" : "=r"(u) : "f"(x));
    return __uint_as_float(u);
}

#define LDSM4(r, a) \
    asm volatile("ldmatrix.sync.aligned.m8n8.x4.shared.b16 {%0,%1,%2,%3}, [%4];" \
                 : "=r"((r)[0]), "=r"((r)[1]), "=r"((r)[2]), "=r"((r)[3]) : "r"(a))

#define CP_ASYNC16(dst, src) \
    asm volatile("cp.async.ca.shared.global [%0], [%1], 16;" :: "r"(dst), "l"(src))
#define CP_COMMIT() asm volatile("cp.async.commit_group;")
#define CP_WAIT(n)  asm volatile("cp.async.wait_group %0;" :: "n"(n))

__device__ __forceinline__ uint32_t smem_u32(const void* p) {
    uint32_t a;
    asm("{ .reg .u64 t; cvta.to.shared.u64 t, %1; cvt.u32.u64 %0, t; }" : "=r"(a) : "l"(p));
    return a;
}

// =====================================================================
// Prep: split fp32 inputs into bf16 hi/lo pairs (memory-bound, ~20us)
// =====================================================================
__device__ __forceinline__ void split4(float4 v, __nv_bfloat16* dh, __nv_bfloat16* dl, size_t e) {
    __nv_bfloat16 h0 = __float2bfloat16(v.x), h1 = __float2bfloat16(v.y);
    __nv_bfloat16 h2 = __float2bfloat16(v.z), h3 = __float2bfloat16(v.w);
    __nv_bfloat162 a, b;
    a.x = h0; a.y = h1; b.x = h2; b.y = h3;
    *reinterpret_cast<__nv_bfloat162*>(dh + e)     = a;
    *reinterpret_cast<__nv_bfloat162*>(dh + e + 2) = b;
    __nv_bfloat162 c, d;
    c.x = __float2bfloat16(v.x - __bfloat162float(h0));
    c.y = __float2bfloat16(v.y - __bfloat162float(h1));
    d.x = __float2bfloat16(v.z - __bfloat162float(h2));
    d.y = __float2bfloat16(v.w - __bfloat162float(h3));
    *reinterpret_cast<__nv_bfloat162*>(dl + e)     = c;
    *reinterpret_cast<__nv_bfloat162*>(dl + e + 2) = d;
}

__global__ __launch_bounds__(256) void prep_kernel(
    const float* __restrict__ x, const float* __restrict__ Wq,
    const float* __restrict__ Wk, const float* __restrict__ Wv,
    const float* __restrict__ Wo)
{
    const int NX = S_LEN * DMODEL / 4;
    const int NW = 3072 * DMODEL / 4;
    const int NO = DMODEL * DMODEL / 4;
    const int total = NX + NW + NO;
    for (int i = blockIdx.x * blockDim.x + threadIdx.x; i < total;
         i += gridDim.x * blockDim.x) {
        if (i < NX) {
            float4 v = reinterpret_cast<const float4*>(x)[i];
            split4(v, g_xh, g_xl, (size_t)i * 4);
        } else if (i < NX + NW) {
            int j = i - NX;
            int row = j >> 9;
            int c4  = j & 511;
            float4 v;
            if (row < 2048)      v = reinterpret_cast<const float4*>(Wq)[row * 512 + c4];
            else if (row < 2560) v = reinterpret_cast<const float4*>(Wk)[(row - 2048) * 512 + c4];
            else                 v = reinterpret_cast<const float4*>(Wv)[(row - 2560) * 512 + c4];
            split4(v, g_wh, g_wl, (size_t)j * 4);
        } else {
            int j = i - NX - NW;
            float4 v = reinterpret_cast<const float4*>(Wo)[j];
            split4(v, g_woh, g_wol, (size_t)j * 4);
        }
    }
}

// =====================================================================
// Tensor-core GEMM v2: cp.async double-buffered, 2 CTAs/SM
//   C[128x128] = A * B^T via bf16 hi/lo 3-term, fp32 accum
//   flavor 0: A=x(hi/lo), B=[Wq;Wk;Wv](hi/lo) -> quant(Q,K)/V store
//   flavor 1: A=attn(hi/lo), B=Wo(hi/lo) -> fp32 out
// =====================================================================
#define GP       80
#define TILE_B   10240
#define STAGE_B  40960        // Ah, Al, Bh, Bl tiles
#define SMEM_DYN 81920        // 2 stages

__global__ __launch_bounds__(256, 2) void tc_gemm(float* __restrict__ outp, int flavor)
{
    extern __shared__ char smem[];
    const uint32_t sbase = smem_u32(smem);
    const int tid  = threadIdx.x;
    const int wid  = tid >> 5;
    const int lane = tid & 31;
    const int m0   = blockIdx.y * 128;
    const int n0   = blockIdx.x * 128;
    const int wm   = (wid & 3) * 32;
    const int wn   = (wid >> 2) * 64;

    const __nv_bfloat16 *aH, *aL, *bH, *bL;
    int mode;                                  // 0=Qquant 1=Kquant 2=V 3=out
    if (flavor == 1) { aH = g_ah; aL = g_al; bH = g_woh; bL = g_wol; mode = 3; }
    else {
        aH = g_xh; aL = g_xl; bH = g_wh; bL = g_wl;
        mode = (n0 < 2048) ? 0 : (n0 < 2560) ? 1 : 2;
    }
    const __nv_bfloat16* srcs[4] = {
        aH + (size_t)m0 * DMODEL, aL + (size_t)m0 * DMODEL,
        bH + (size_t)n0 * DMODEL, bL + (size_t)n0 * DMODEL };

    // per-thread cp.async: 2 chunks (16B) per tile per stage
    const int crow0 = tid >> 1;                 // chunks 0..511: row = c>>2
    // chunk c = tid  -> row tid>>2, seg tid&3 ; chunk c = tid+256 -> row 64+(tid>>2)
    // ldmatrix addresses
    const uint32_t aAddr = sbase + (wm + (lane & 15)) * GP + ((lane >> 4) << 4);
    const uint32_t bAddr = sbase + 2 * TILE_B +
        (wn + (lane & 7) + ((lane >> 4) & 1) * 8) * GP + (((lane >> 3) & 1) << 4);
    (void)crow0;

    float acc[2][8][4];
#pragma unroll
    for (int mt = 0; mt < 2; mt++)
#pragma unroll
        for (int nt = 0; nt < 8; nt++)
#pragma unroll
            for (int i = 0; i < 4; i++) acc[mt][nt][i] = 0.f;

    const int r0 = tid >> 2, s0 = tid & 3;      // chunk tid
    // stage loader: kc = element offset in K
    auto load_stage = [&](int it, int buf) {
        const int kc = it * 32;
        const uint32_t db = sbase + buf * STAGE_B;
#pragma unroll
        for (int t = 0; t < 4; t++) {
            const __nv_bfloat16* s = srcs[t];
            uint32_t d0 = db + t * TILE_B + r0 * GP + s0 * 16;
            CP_ASYNC16(d0, (const char*)(s + (size_t)r0 * DMODEL + kc) + s0 * 16);
            uint32_t d1 = db + t * TILE_B + (r0 + 64) * GP + s0 * 16;
            CP_ASYNC16(d1, (const char*)(s + (size_t)(r0 + 64) * DMODEL + kc) + s0 * 16);
        }
    };

    load_stage(0, 0); CP_COMMIT();
    load_stage(1, 1); CP_COMMIT();

    for (int it = 0; it < 64; it++) {
        const int buf = it & 1;
        if (it == 63) CP_WAIT(0); else CP_WAIT(1);
        __syncthreads();

        const uint32_t ab = aAddr + buf * STAGE_B;
        const uint32_t bb = bAddr + buf * STAGE_B;
#pragma unroll
        for (int s = 0; s < 2; s++) {
            uint32_t ah[2][4], al[2][4], bh[4][4], bl[4][4];
#pragma unroll
            for (int mt = 0; mt < 2; mt++) {
                LDSM4(ah[mt], ab + mt * (16 * GP) + s * 32);
                LDSM4(al[mt], ab + mt * (16 * GP) + s * 32 + TILE_B);
            }
#pragma unroll
            for (int np = 0; np < 4; np++) {
                LDSM4(bh[np], bb + np * (16 * GP) + s * 32);
                LDSM4(bl[np], bb + np * (16 * GP) + s * 32 + TILE_B);
            }
#pragma unroll
            for (int mt = 0; mt < 2; mt++)
#pragma unroll
                for (int nt = 0; nt < 8; nt++) {
                    uint32_t h0 = bh[nt >> 1][(nt & 1) * 2];
                    uint32_t h1 = bh[nt >> 1][(nt & 1) * 2 + 1];
                    uint32_t l0 = bl[nt >> 1][(nt & 1) * 2];
                    uint32_t l1 = bl[nt >> 1][(nt & 1) * 2 + 1];
                    mma_bf16(acc[mt][nt], ah[mt], h0, h1);
                    mma_bf16(acc[mt][nt], ah[mt], l0, l1);
                    mma_bf16(acc[mt][nt], al[mt], h0, h1);
                }
        }
        __syncthreads();
        if (it < 62) { load_stage(it + 2, buf); CP_COMMIT(); }
    }

    // ---- epilogue ----
    const int qrow = lane >> 2;
    const int qcol = (lane & 3) * 2;
#pragma unroll
    for (int mt = 0; mt < 2; mt++) {
#pragma unroll
        for (int h = 0; h < 2; h++) {
            const int row = m0 + wm + mt * 16 + qrow + h * 8;
            if (mode <= 1) {
                float am = 0.f;
#pragma unroll
                for (int nt = 0; nt < 8; nt++)
                    am = fmaxf(am, fmaxf(fabsf(acc[mt][nt][h * 2]),
                                         fabsf(acc[mt][nt][h * 2 + 1])));
                am = fmaxf(am, __shfl_xor_sync(0xffffffffu, am, 1));
                am = fmaxf(am, __shfl_xor_sync(0xffffffffu, am, 2));
                float scale = 127.f / fmaxf(am, 1e-6f);
#pragma unroll
                for (int nt = 0; nt < 8; nt++) {
                    int v0 = min(127, max(-127, __float2int_rn(acc[mt][nt][h * 2]     * scale)));
                    int v1 = min(127, max(-127, __float2int_rn(acc[mt][nt][h * 2 + 1] * scale)));
                    unsigned short pk = (unsigned short)((v0 & 255) | ((v1 & 255) << 8));
                    if (mode == 0)
                        *reinterpret_cast<unsigned short*>(
                            &g_q8[(size_t)row * DMODEL + n0 + wn + nt * 8 + qcol]) = pk;
                    else
                        *reinterpret_cast<unsigned short*>(
                            &g_k8[(size_t)row * DKV + (n0 - 2048) + wn + nt * 8 + qcol]) = pk;
                }
                if ((lane & 3) == 0) {
                    if (mode == 0) g_qs[row * NH  + ((n0 + wn) >> 6)]        = scale;
                    else           g_ks[row * NKV + ((n0 - 2048 + wn) >> 6)] = scale;
                }
            } else {
#pragma unroll
                for (int nt = 0; nt < 8; nt++) {
                    float2 v = make_float2(acc[mt][nt][h * 2], acc[mt][nt][h * 2 + 1]);
                    if (mode == 2)
                        *reinterpret_cast<float2*>(
                            &g_v[(size_t)row * DKV + (n0 - 2560) + wn + nt * 8 + qcol]) = v;
                    else
                        *reinterpret_cast<float2*>(
                            &outp[(size_t)row * DMODEL + n0 + wn + nt * 8 + qcol]) = v;
                }
            }
        }
    }
}

// =====================================================================
// Attention kernel (round-2 design; epilogue writes bf16 hi/lo)
// =====================================================================
__global__ __launch_bounds__(128) void attn_kernel()
{
    const int h    = blockIdx.y;
    const int qb   = gridDim.x - 1 - blockIdx.x;
    const int kvh  = h >> 2;
    const int tid  = threadIdx.x;
    const int warp = tid >> 5;
    const int lane = tid & 31;
    const int g    = lane >> 2;
    const int tg   = lane & 3;
    const int rbase = warp * 16;

    __shared__ int   qsm[64][20];
    __shared__ int   ksm[64][20];
    __shared__ float vsm[64][72];
    __shared__ float psm[64][68];
    __shared__ float qfac[64];
    __shared__ float kinv[64];

#pragma unroll
    for (int i = 0; i < 2; i++) {
        int idx = tid + i * 128;
        int row = idx >> 2;
        int seg = idx & 3;
        int4 v = *reinterpret_cast<const int4*>(
            &g_q8[(size_t)(qb * 64 + row) * DMODEL + h * 64 + seg * 16]);
        *reinterpret_cast<int4*>(&qsm[row][seg * 4]) = v;
    }
    if (tid < 64) qfac[tid] = 0.125f / g_qs[(qb * 64 + tid) * NH + h];
    __syncthreads();

    int qa[2][4];
#pragma unroll
    for (int s = 0; s < 2; s++) {
        qa[s][0] = qsm[rbase + g    ][s * 8 + tg];
        qa[s][1] = qsm[rbase + g + 8][s * 8 + tg];
        qa[s][2] = qsm[rbase + g    ][s * 8 + 4 + tg];
        qa[s][3] = qsm[rbase + g + 8][s * 8 + 4 + tg];
    }

    const int   rowA = rbase + g, rowB = rowA + 8;
    const float qfA  = qfac[rowA], qfB = qfac[rowB];
    const int   qgA  = qb * 64 + rowA, qgB = qb * 64 + rowB;

    float acc[8][4];
#pragma unroll
    for (int nt = 0; nt < 8; nt++)
#pragma unroll
        for (int i = 0; i < 4; i++) acc[nt][i] = 0.f;
    float m_runA = NEG_INF, m_runB = NEG_INF;
    float l_runA = 0.f,     l_runB = 0.f;

    for (int j = 0; j <= qb; j++) {
#pragma unroll
        for (int i = 0; i < 2; i++) {
            int idx = tid + i * 128;
            int row = idx >> 2;
            int seg = idx & 3;
            int4 v = *reinterpret_cast<const int4*>(
                &g_k8[(size_t)(j * 64 + row) * DKV + kvh * 64 + seg * 16]);
            *reinterpret_cast<int4*>(&ksm[row][seg * 4]) = v;
        }
        if (tid < 64) kinv[tid] = 1.f / g_ks[(j * 64 + tid) * NKV + kvh];
#pragma unroll
        for (int i = 0; i < 8; i++) {
            int idx = tid + i * 128;
            int row = idx >> 4;
            int c4  = (idx & 15) << 2;
            float4 vv = *reinterpret_cast<const float4*>(
                &g_v[(size_t)(j * 64 + row) * DKV + kvh * 64 + c4]);
            vv.x = tf32r(vv.x); vv.y = tf32r(vv.y);
            vv.z = tf32r(vv.z); vv.w = tf32r(vv.w);
            *reinterpret_cast<float4*>(&vsm[row][c4]) = vv;
        }
        __syncthreads();

        int sc[8][4];
#pragma unroll
        for (int nt = 0; nt < 8; nt++) {
            sc[nt][0] = sc[nt][1] = sc[nt][2] = sc[nt][3] = 0;
#pragma unroll
            for (int s = 0; s < 2; s++) {
                int b0 = ksm[nt * 8 + g][s * 8 + tg];
                int b1 = ksm[nt * 8 + g][s * 8 + 4 + tg];
                mma_s8(sc[nt], qa[s], b0, b1);
            }
        }

        const bool maskblk = (j == qb);
        float sv[8][4];
        float mxA = NEG_INF, mxB = NEG_INF;
#pragma unroll
        for (int nt = 0; nt < 8; nt++) {
            int colbase = nt * 8 + tg * 2;
            float2 kv = *reinterpret_cast<const float2*>(&kinv[colbase]);
            float s0 = (float)sc[nt][0] * qfA * kv.x;
            float s1 = (float)sc[nt][1] * qfA * kv.y;
            float s2 = (float)sc[nt][2] * qfB * kv.x;
            float s3 = (float)sc[nt][3] * qfB * kv.y;
            if (maskblk) {
                int col = j * 64 + colbase;
                if (col     > qgA) s0 = NEG_INF;
                if (col + 1 > qgA) s1 = NEG_INF;
                if (col     > qgB) s2 = NEG_INF;
                if (col + 1 > qgB) s3 = NEG_INF;
            }
            sv[nt][0] = s0; sv[nt][1] = s1; sv[nt][2] = s2; sv[nt][3] = s3;
            mxA = fmaxf(mxA, fmaxf(s0, s1));
            mxB = fmaxf(mxB, fmaxf(s2, s3));
        }
        mxA = fmaxf(mxA, __shfl_xor_sync(0xffffffffu, mxA, 1));
        mxA = fmaxf(mxA, __shfl_xor_sync(0xffffffffu, mxA, 2));
        mxB = fmaxf(mxB, __shfl_xor_sync(0xffffffffu, mxB, 1));
        mxB = fmaxf(mxB, __shfl_xor_sync(0xffffffffu, mxB, 2));

        float mA = fmaxf(m_runA, mxA);
        float mB = fmaxf(m_runB, mxB);
        float aA = __expf(m_runA - mA);
        float aB = __expf(m_runB - mB);
        m_runA = mA; m_runB = mB;

        float sumA = 0.f, sumB = 0.f;
#pragma unroll
        for (int nt = 0; nt < 8; nt++) {
            int colbase = nt * 8 + tg * 2;
            float p0 = __expf(sv[nt][0] - mA);
            float p1 = __expf(sv[nt][1] - mA);
            float p2 = __expf(sv[nt][2] - mB);
            float p3 = __expf(sv[nt][3] - mB);
            sumA += p0 + p1; sumB += p2 + p3;
            float2 w0 = make_float2(tf32r(p0), tf32r(p1));
            float2 w1 = make_float2(tf32r(p2), tf32r(p3));
            *reinterpret_cast<float2*>(&psm[rowA][colbase]) = w0;
            *reinterpret_cast<float2*>(&psm[rowB][colbase]) = w1;
        }
        sumA += __shfl_xor_sync(0xffffffffu, sumA, 1);
        sumA += __shfl_xor_sync(0xffffffffu, sumA, 2);
        sumB += __shfl_xor_sync(0xffffffffu, sumB, 1);
        sumB += __shfl_xor_sync(0xffffffffu, sumB, 2);
        l_runA = l_runA * aA + sumA;
        l_runB = l_runB * aB + sumB;

#pragma unroll
        for (int nt = 0; nt < 8; nt++) {
            acc[nt][0] *= aA; acc[nt][1] *= aA;
            acc[nt][2] *= aB; acc[nt][3] *= aB;
        }

        __syncwarp();

#pragma unroll
        for (int ks = 0; ks < 8; ks++) {
            unsigned pa0 = __float_as_uint(psm[rowA][ks * 8 + tg]);
            unsigned pa1 = __float_as_uint(psm[rowB][ks * 8 + tg]);
            unsigned pa2 = __float_as_uint(psm[rowA][ks * 8 + 4 + tg]);
            unsigned pa3 = __float_as_uint(psm[rowB][ks * 8 + 4 + tg]);
#pragma unroll
            for (int nt = 0; nt < 8; nt++) {
                unsigned b0 = __float_as_uint(vsm[ks * 8 + tg    ][nt * 8 + g]);
                unsigned b1 = __float_as_uint(vsm[ks * 8 + tg + 4][nt * 8 + g]);
                mma_tf32(acc[nt], pa0, pa1, pa2, pa3, b0, b1);
            }
        }

        __syncthreads();
    }

    // ---- epilogue: write bf16 hi/lo for the tensor-core out-projection ----
    float ilA = 1.f / l_runA, ilB = 1.f / l_runB;
#pragma unroll
    for (int nt = 0; nt < 8; nt++) {
        int colbase = nt * 8 + tg * 2;
        float oA0 = acc[nt][0] * ilA, oA1 = acc[nt][1] * ilA;
        float oB0 = acc[nt][2] * ilB, oB1 = acc[nt][3] * ilB;
        size_t pA = (size_t)qgA * DMODEL + h * 64 + colbase;
        size_t pB = (size_t)qgB * DMODEL + h * 64 + colbase;
        __nv_bfloat162 hA, hB, lA, lB;
        hA.x = __float2bfloat16(oA0); hA.y = __float2bfloat16(oA1);
        hB.x = __float2bfloat16(oB0); hB.y = __float2bfloat16(oB1);
        lA.x = __float2bfloat16(oA0 - __bfloat162float(hA.x));
        lA.y = __float2bfloat16(oA1 - __bfloat162float(hA.y));
        lB.x = __float2bfloat16(oB0 - __bfloat162float(hB.x));
        lB.y = __float2bfloat16(oB1 - __bfloat162float(hB.y));
        *reinterpret_cast<__nv_bfloat162*>(&g_ah[pA]) = hA;
        *reinterpret_cast<__nv_bfloat162*>(&g_al[pA]) = lA;
        *reinterpret_cast<__nv_bfloat162*>(&g_ah[pB]) = hB;
        *reinterpret_cast<__nv_bfloat162*>(&g_al[pB]) = lB;
    }
}

// =====================================================================
extern "C" void kernel_launch(void* const* d_in, const int* in_sizes, int n_in,
                              void* d_out, int out_size)
{
    const float* x  = (const float*)d_in[0];
    const float* Wq = (const float*)d_in[1];
    const float* Wk = (const float*)d_in[2];
    const float* Wv = (const float*)d_in[3];
    const float* Wo = (const float*)d_in[4];
    float* out = (float*)d_out;

    cudaFuncSetAttribute(tc_gemm, cudaFuncAttributeMaxDynamicSharedMemorySize, SMEM_DYN);

    prep_kernel<<<592, 256>>>(x, Wq, Wk, Wv, Wo);
    tc_gemm<<<dim3(24, 16), 256, SMEM_DYN>>>(nullptr, 0);   // QKV + quant
    attn_kernel<<<dim3(32, 32), 128>>>();
    tc_gemm<<<dim3(16, 16), 256, SMEM_DYN>>>(out, 1);       // output projection
}